// round 7
// baseline (speedup 1.0000x reference)
#include <cuda_runtime.h>
#include <math.h>

#define HH 128
#define WW 128
#define NPIX (HH * WW)
#define NPTS 16384
#define KNN 16
#define FDIM 64
#define CAP 12
#define OVFCAP 512
#define FULLMASK 0xffffffffu

#define OFF_DEPTH 0
#define OFF_COLOR (NPIX)
#define OFF_FEAT  (NPIX + NPIX * 3)
#define OFF_MASK  (NPIX + NPIX * 3 + NPIX * FDIM)

// ---- device scratch ----
__device__ int    g_cnt[NPIX + 1];
__device__ float4 g_bucket[NPIX * CAP];
__device__ float4 g_ovf[OVFCAP];

__global__ void __launch_bounds__(256) project_bin_kernel(
    const float* __restrict__ pts, const float* __restrict__ intr) {
    int i = blockIdx.x * 256 + threadIdx.x;
    if (i >= NPTS) return;
    float x = __ldg(&pts[3 * i + 0]);
    float y = __ldg(&pts[3 * i + 1]);
    float z = __ldg(&pts[3 * i + 2]);
    float fx = intr[0], cx = intr[2], fy = intr[4], cy = intr[5];
    bool valid = z > 1e-6f;
    float sz = valid ? z : 1.0f;
    float u = __fadd_rn(__fdiv_rn(__fmul_rn(x, fx), sz), cx);
    float v = __fadd_rn(__fdiv_rn(__fmul_rn(y, fy), sz), cy);
    if (!valid) { u = 1e9f; v = 1e9f; }
    if (u > -2.0f && u < 130.0f && v > -2.0f && v < 130.0f) {
        int cu = min(max((int)floorf(u), 0), WW - 1);
        int cv = min(max((int)floorf(v), 0), HH - 1);
        int cell = cv * WW + cu;
        float4 rec = make_float4(u, v, z, __int_as_float(i));
        int pos = atomicAdd(&g_cnt[cell], 1);
        if (pos < CAP) {
            g_bucket[cell * CAP + pos] = rec;
        } else {
            int o = atomicAdd(&g_cnt[NPIX], 1);
            if (o < OVFCAP) g_ovf[o] = rec;
        }
    }
}

// warp per pixel: 16384 warps, 2048 blocks x 256
__global__ void __launch_bounds__(256) knn_feat_kernel(
    const float* __restrict__ colors, const float* __restrict__ feats,
    float* __restrict__ out) {
    __shared__ int    s_map[8][64];    // candidate j -> bucket slot index
    __shared__ float4 s_c[8][KNN];     // compacted {wn, z, bitcast(id), -}
    __shared__ int    s_fn[8];

    int lane = threadIdx.x & 31;
    int warp = threadIdx.x >> 5;
    int p = blockIdx.x * 8 + warp;
    int pi = p >> 7, pj = p & 127;
    float px = pj + 0.5f, py = pi + 0.5f;

    // lane -> neighbor cell (5x5)
    int rr = lane / 5, qq = lane - 5 * rr;
    int cv = pi - 2 + rr, cu = pj - 2 + qq;
    bool cok = (lane < 25) && (cv >= 0) && (cv < HH) && (cu >= 0) && (cu < WW);
    int cell = cok ? (cv * WW + cu) : 0;
    int cnt = cok ? min(g_cnt[cell], CAP) : 0;

    // warp inclusive scan of counts
    int incl = cnt;
#pragma unroll
    for (int o = 1; o < 32; o <<= 1) {
        int v = __shfl_up_sync(FULLMASK, incl, o);
        if (lane >= o) incl += v;
    }
    int T = __shfl_sync(FULLMASK, incl, 31);
    int excl = incl - cnt;
    int novf = g_cnt[NPIX];

    bool fastpath = (T <= 64) && (novf == 0);
    unsigned lmask = (1u << lane) - 1u;

    if (fastpath) {
        // build inverse map: candidate j -> bucket slot (avg 1 store per lane)
        int base = cell * CAP;
        for (int i = 0; i < cnt; ++i) s_map[warp][excl + i] = base + i;
        __syncwarp();

        float d2_0 = 4.0f, d2_1 = 4.0f, z0 = 0.0f, z1 = 0.0f;
        int id0 = 0, id1 = 0;
        bool act0 = false, act1 = false;

        if (lane < T) {
            float4 rec = g_bucket[s_map[warp][lane]];
            float du = __fsub_rn(px, rec.x);
            float dv = __fsub_rn(py, rec.y);
            float d2 = __fadd_rn(__fmul_rn(du, du), __fmul_rn(dv, dv));
            if (d2 < 4.0f) { act0 = true; d2_0 = d2; z0 = rec.z; id0 = __float_as_int(rec.w); }
        }
        if (T > 32) {
            if (lane + 32 < T) {
                float4 rec = g_bucket[s_map[warp][lane + 32]];
                float du = __fsub_rn(px, rec.x);
                float dv = __fsub_rn(py, rec.y);
                float d2 = __fadd_rn(__fmul_rn(du, du), __fmul_rn(dv, dv));
                if (d2 < 4.0f) { act1 = true; d2_1 = d2; z1 = rec.z; id1 = __float_as_int(rec.w); }
            }
        }

        // exact top-16 eviction (rare; warp-uniform loop condition)
        int m = __popc(__ballot_sync(FULLMASK, act0)) + __popc(__ballot_sync(FULLMASK, act1));
        while (m > KNN) {
            float lm = -1.0f;
            if (act0) lm = d2_0;
            if (act1 && d2_1 > lm) lm = d2_1;
            float gm = lm;
#pragma unroll
            for (int o = 16; o; o >>= 1)
                gm = fmaxf(gm, __shfl_xor_sync(FULLMASK, gm, o));
            unsigned v1 = __ballot_sync(FULLMASK, act1 && d2_1 == gm);
            unsigned v0 = __ballot_sync(FULLMASK, act0 && d2_0 == gm);
            if (v1) { if (lane == 31 - __clz(v1)) act1 = false; }
            else    { if (lane == 31 - __clz(v0)) act0 = false; }
            --m;
        }

        // weight-sum reduction (the only reduction needed)
        float w0 = act0 ? __expf(-d2_0) : 0.0f;
        float w1 = act1 ? __expf(-d2_1) : 0.0f;
        float ws = w0 + w1;
#pragma unroll
        for (int o = 16; o; o >>= 1)
            ws += __shfl_xor_sync(FULLMASK, ws, o);
        float winv = 1.0f / (ws + 1e-10f);

        // compact {wn, z, id} into smem
        unsigned ball0 = __ballot_sync(FULLMASK, act0);
        unsigned ball1 = __ballot_sync(FULLMASK, act1);
        int n0 = __popc(ball0);
        if (act0) s_c[warp][__popc(ball0 & lmask)] =
            make_float4(w0 * winv, z0, __int_as_float(id0), 0.0f);
        if (act1) s_c[warp][n0 + __popc(ball1 & lmask)] =
            make_float4(w1 * winv, z1, __int_as_float(id1), 0.0f);
        if (lane == 0) s_fn[warp] = n0 + __popc(ball1);
    } else {
        // exact scalar fallback (lane 0); warp-uniform path condition
        if (lane == 0) {
            float d2s[KNN], zs[KNN];
            int ids[KNN];
            int n = 0;
            float curmax = -1.0f;
            int argmax = 0;
            int cv0 = max(pi - 2, 0), cv1 = min(pi + 2, HH - 1);
            int cu0 = max(pj - 2, 0), cu1 = min(pj + 2, WW - 1);
            int no = min(novf, OVFCAP);
            for (int a = cv0; a <= cv1 + 1; ++a) {
                bool op = (a == cv1 + 1);
                int blo = op ? 0 : cu0, bhi = op ? 0 : cu1;
                for (int b = blo; b <= bhi; ++b) {
                    int cc;
                    const float4* bk;
                    if (op) { cc = no; bk = g_ovf; }
                    else { int ce = a * WW + b; cc = min(g_cnt[ce], CAP); bk = &g_bucket[ce * CAP]; }
                    for (int s = 0; s < cc; ++s) {
                        float4 rec = bk[s];
                        float du = __fsub_rn(px, rec.x);
                        float dv = __fsub_rn(py, rec.y);
                        float d2 = __fadd_rn(__fmul_rn(du, du), __fmul_rn(dv, dv));
                        if (d2 >= 4.0f) continue;
                        if (n < KNN) {
                            d2s[n] = d2; zs[n] = rec.z; ids[n] = __float_as_int(rec.w);
                            if (d2 > curmax) { curmax = d2; argmax = n; }
                            ++n;
                        } else if (d2 < curmax) {
                            d2s[argmax] = d2; zs[argmax] = rec.z; ids[argmax] = __float_as_int(rec.w);
                            curmax = -1.0f;
                            for (int k = 0; k < KNN; ++k)
                                if (d2s[k] > curmax) { curmax = d2s[k]; argmax = k; }
                        }
                    }
                }
            }
            float ws = 0.0f;
            for (int k = 0; k < n; ++k) { d2s[k] = __expf(-d2s[k]); ws += d2s[k]; }
            float winv = 1.0f / (ws + 1e-10f);
            for (int k = 0; k < n; ++k)
                s_c[warp][k] = make_float4(d2s[k] * winv, zs[k], __int_as_float(ids[k]), 0.0f);
            s_fn[warp] = n;
        }
    }
    __syncwarp();

    // ---- unified gather: feats (all lanes), colors (lanes 0-2), depth (all) ----
    int n = s_fn[warp];
    float fa0 = 0.0f, fa1 = 0.0f, dacc = 0.0f, cacc = 0.0f;
#pragma unroll 4
    for (int k = 0; k < n; ++k) {
        float4 c = s_c[warp][k];          // LDS.128 broadcast
        float wn = c.x;
        int id = __float_as_int(c.z);
        const float* f = feats + (size_t)id * FDIM;
        fa0 += wn * __ldg(f + lane);
        fa1 += wn * __ldg(f + lane + 32);
        dacc += wn * c.y;
        if (lane < 3) cacc += wn * __ldg(&colors[3 * id + lane]);
    }
    out[OFF_FEAT + (size_t)p * FDIM + lane] = fa0;
    out[OFF_FEAT + (size_t)p * FDIM + lane + 32] = fa1;
    if (lane < 3) out[OFF_COLOR + 3 * p + lane] = cacc;
    if (lane == 3) out[OFF_DEPTH + p] = dacc;
    if (lane == 4) out[OFF_MASK + p] = (n > 0) ? 1.0f : 0.0f;
}

extern "C" void kernel_launch(void* const* d_in, const int* in_sizes, int n_in,
                              void* d_out, int out_size) {
    const float* pts    = (const float*)d_in[0];
    const float* colors = (const float*)d_in[1];
    const float* feats  = (const float*)d_in[2];
    const float* intr   = (const float*)d_in[3];
    float* out = (float*)d_out;

    void* p_cnt = nullptr;
    cudaGetSymbolAddress(&p_cnt, g_cnt);
    cudaMemsetAsync(p_cnt, 0, sizeof(int) * (NPIX + 1), 0);

    project_bin_kernel<<<NPTS / 256, 256>>>(pts, intr);
    knn_feat_kernel<<<NPIX / 8, 256>>>(colors, feats, out);
}